// round 9
// baseline (speedup 1.0000x reference)
#include <cuda_runtime.h>
#include <cuda_bf16.h>

// ManifoldConstrainedHyperConnection — fused, G=8 token groups,
// warp-specialized router, same-iteration mix (short L2 reuse distance).
//
// 576 threads/CTA = 16 worker warps (512 thr) + 2 router warps (64 thr).
// Workers per group: [A: load x (ld.cg) -> means in regs] -> [B: 6 FMA +
// butterfly sets -> sP, arrive FULL(s)] -> [prefetch next group, preload
// 2 tokens' mix operands] -> [sync DONE(s)] -> [F: mix + store, same iter].
// Routers: sync FULL(s) -> reduce 192 partials -> scalar sinkhorn (1 token
// per lane, lanes 0-3 of each router warp) -> write M -> arrive DONE(s).
// Wr (192KB) in smem; 4-float d-slice per worker thread.

#define WRK 24
#define DDIM 2048
#define WS 4
#define THREADS 576
#define WWARPS 16
#define G 8
#define EPSV 1e-6f

#define SP_STRIDE 200
#define SP_SLOT (WWARPS * SP_STRIDE)        // 3200 floats/slot
#define SMEM_WR (WRK * DDIM)                // 49152 floats
#define OFF_SP   SMEM_WR
#define OFF_RAW  (OFF_SP + 2 * SP_SLOT)     // 2 x 192
#define OFF_M    (OFF_RAW + 2 * 192)        // 2 x 128
#define SMEM_FLOATS (OFF_M + 2 * 128)
#define SMEM_BYTES (SMEM_FLOATS * 4)        // ~224.8 KB

#define FULLM 0xffffffffu

// named barriers: FULL_s = 1+s (workers arrive, routers sync),
//                 DONE_s = 3+s (routers arrive, workers sync), router-int 5
#define BAR_ARRIVE(id)    asm volatile("bar.arrive %0, %1;" :: "r"(id), "r"(THREADS) : "memory")
#define BAR_SYNC_ALL(id)  asm volatile("bar.sync %0, %1;"   :: "r"(id), "r"(THREADS) : "memory")
#define BAR_SYNC_R(id)    asm volatile("bar.sync %0, %1;"   :: "r"(id), "r"(64) : "memory")

__device__ __forceinline__ float4 ld_cg4(const float* p) {
    return __ldcg(reinterpret_cast<const float4*>(p));
}

#define BFLY_STEP(r, n, o)                                              \
    {                                                                   \
        const bool hi_ = (lane & (o)) != 0;                             \
        _Pragma("unroll")                                               \
        for (int v_ = 0; v_ < (n) / 2; v_++) {                          \
            float mine_  = hi_ ? r[v_ + (n) / 2] : r[v_];               \
            float other_ = hi_ ? r[v_] : r[v_ + (n) / 2];               \
            r[v_] = mine_ + __shfl_xor_sync(FULLM, other_, (o));        \
        }                                                               \
    }

__global__ void __launch_bounds__(THREADS, 1)
mchc_kernel(const float* __restrict__ x, const float* __restrict__ Wr,
            const float* __restrict__ br, float* __restrict__ out, int ntok)
{
    extern __shared__ float sm[];
    float* sWr = sm;

    const int tid  = threadIdx.x;
    const int lane = tid & 31;
    const int warp = tid >> 5;

    for (int i = tid * 4; i < SMEM_WR; i += THREADS * 4)
        *reinterpret_cast<float4*>(sWr + i) = *reinterpret_cast<const float4*>(Wr + i);
    __syncthreads();

    const int ngroups = (ntok + G - 1) / G;
    const int gstride = gridDim.x;

    if (warp < WWARPS) {
        // ================= WORKER PATH (512 threads) =================
        const int d0 = tid * 4;
        int it = 0;

        for (int g = blockIdx.x; g < ngroups; g += gstride, it++) {
            const int s  = it & 1;
            const int n0 = g * G;
            float* sP = sm + OFF_SP + s * SP_SLOT;
            const float* sM = sm + OFF_M + s * 128;

            // ---- A: load x (ld.cg), accumulate stream means ----
            float4 mx[G];
            #pragma unroll
            for (int t = 0; t < G; t++) {
                mx[t] = make_float4(0.f, 0.f, 0.f, 0.f);
                if (n0 + t < ntok) {
                    const float* p = x + (size_t)(n0 + t) * (WS * DDIM) + d0;
                    #pragma unroll
                    for (int w = 0; w < WS; w++) {
                        float4 v = ld_cg4(p + w * DDIM);
                        mx[t].x += v.x; mx[t].y += v.y; mx[t].z += v.z; mx[t].w += v.w;
                    }
                    mx[t].x *= 0.25f; mx[t].y *= 0.25f;
                    mx[t].z *= 0.25f; mx[t].w *= 0.25f;
                }
            }

            // ---- B: 6 sets x (4 rows x 8 tokens) partials + butterfly ----
            float res[6];
            #pragma unroll
            for (int set = 0; set < 6; set++) {
                float a[32];
                #pragma unroll
                for (int kk = 0; kk < 4; kk++) {
                    const int k = 4 * set + kk;
                    float4 wr = *reinterpret_cast<const float4*>(sWr + k * DDIM + d0);
                    #pragma unroll
                    for (int t = 0; t < G; t++)
                        a[kk * 8 + t] = wr.x * mx[t].x + wr.y * mx[t].y +
                                        wr.z * mx[t].z + wr.w * mx[t].w;
                }
                BFLY_STEP(a, 32, 16)
                BFLY_STEP(a, 16, 8)
                BFLY_STEP(a, 8, 4)
                BFLY_STEP(a, 4, 2)
                BFLY_STEP(a, 2, 1)
                res[set] = a[0];    // lane l holds warp-sum of value 32*set + l
            }
            #pragma unroll
            for (int set = 0; set < 6; set++)
                sP[warp * SP_STRIDE + 32 * set + lane] = res[set];
            BAR_ARRIVE(1 + s);                      // publish sP[s]

            // ---- warm next group's x into L2 (256KB = 512 thr x 512B) ----
            {
                const int gn = g + gstride;
                if (gn < ngroups) {
                    const char* pb = reinterpret_cast<const char*>(
                                         x + (size_t)gn * G * (WS * DDIM)) + tid * 512;
                    asm volatile("prefetch.global.L2 [%0];" :: "l"(pb));
                    asm volatile("prefetch.global.L2 [%0];" :: "l"(pb + 128));
                    asm volatile("prefetch.global.L2 [%0];" :: "l"(pb + 256));
                    asm volatile("prefetch.global.L2 [%0];" :: "l"(pb + 384));
                }
            }

            // ---- preload tokens 0-1 mix operands (independent of M) ----
            float4 pre0[WS], pre1[WS];
            {
                const float* p0 = x + (size_t)(n0 + 0) * (WS * DDIM) + d0;
                const float* p1 = x + (size_t)(n0 + 1) * (WS * DDIM) + d0;
                const bool ok0 = (n0 + 0) < ntok, ok1 = (n0 + 1) < ntok;
                #pragma unroll
                for (int w = 0; w < WS; w++) {
                    pre0[w] = ok0 ? ld_cg4(p0 + w * DDIM) : make_float4(0,0,0,0);
                    pre1[w] = ok1 ? ld_cg4(p1 + w * DDIM) : make_float4(0,0,0,0);
                }
            }

            BAR_SYNC_ALL(3 + s);                    // wait for M (routers)

            // ---- F: mix + store (same iteration; x re-reads are L2 hits) ----
            #pragma unroll
            for (int t = 0; t < 2; t++) {
                if (n0 + t < ntok) {
                    float* o = out + (size_t)(n0 + t) * (WS * DDIM) + d0;
                    const float4* xv = (t == 0) ? pre0 : pre1;
                    #pragma unroll
                    for (int i = 0; i < WS; i++) {
                        float4 Mi = *reinterpret_cast<const float4*>(sM + t * 16 + i * 4);
                        float4 ov;
                        ov.x = Mi.x*xv[0].x + Mi.y*xv[1].x + Mi.z*xv[2].x + Mi.w*xv[3].x;
                        ov.y = Mi.x*xv[0].y + Mi.y*xv[1].y + Mi.z*xv[2].y + Mi.w*xv[3].y;
                        ov.z = Mi.x*xv[0].z + Mi.y*xv[1].z + Mi.z*xv[2].z + Mi.w*xv[3].z;
                        ov.w = Mi.x*xv[0].w + Mi.y*xv[1].w + Mi.z*xv[2].w + Mi.w*xv[3].w;
                        __stcs(reinterpret_cast<float4*>(o + i * DDIM), ov);
                    }
                }
            }
            #pragma unroll
            for (int t = 2; t < G; t++) {
                if (n0 + t < ntok) {
                    const float* p = x + (size_t)(n0 + t) * (WS * DDIM) + d0;
                    float*       o = out + (size_t)(n0 + t) * (WS * DDIM) + d0;
                    float4 x0 = ld_cg4(p);
                    float4 x1 = ld_cg4(p + DDIM);
                    float4 x2 = ld_cg4(p + 2 * DDIM);
                    float4 x3 = ld_cg4(p + 3 * DDIM);
                    #pragma unroll
                    for (int i = 0; i < WS; i++) {
                        float4 Mi = *reinterpret_cast<const float4*>(sM + t * 16 + i * 4);
                        float4 ov;
                        ov.x = Mi.x*x0.x + Mi.y*x1.x + Mi.z*x2.x + Mi.w*x3.x;
                        ov.y = Mi.x*x0.y + Mi.y*x1.y + Mi.z*x2.y + Mi.w*x3.y;
                        ov.z = Mi.x*x0.z + Mi.y*x1.z + Mi.z*x2.z + Mi.w*x3.z;
                        ov.w = Mi.x*x0.w + Mi.y*x1.w + Mi.z*x2.w + Mi.w*x3.w;
                        __stcs(reinterpret_cast<float4*>(o + i * DDIM), ov);
                    }
                }
            }
            // slot s is rewritten two iterations later; routers finished it
            // before DONE(s), so no extra barrier needed.
        }
    } else {
        // ================= ROUTER PATH (warps 16-17) =================
        const int rwarp = warp - WWARPS;      // 0 or 1
        int it = 0;

        for (int g = blockIdx.x; g < ngroups; g += gstride, it++) {
            const int s = it & 1;
            float* sP   = sm + OFF_SP + s * SP_SLOT;
            float* sRaw = sm + OFF_RAW + s * 192;
            float* sM   = sm + OFF_M + s * 128;

            asm volatile("bar.sync %0, %1;" :: "r"(1 + s), "r"(THREADS) : "memory"); // FULL_s

            // reduce 192 values over 16 worker warps; value v = 8k + t
            #pragma unroll
            for (int j = 0; j < 3; j++) {
                const int v = 96 * rwarp + 32 * j + lane;
                float acc = __ldg(br + (v >> 3));
                #pragma unroll
                for (int w = 0; w < WWARPS; w++)
                    acc += sP[w * SP_STRIDE + v];
                sRaw[v] = acc;
            }
            BAR_SYNC_R(5);                            // both router warps see sRaw

            // scalar softmax + sinkhorn: lane l<4 handles token t = 4*rwarp + l
            {
                const int t = 4 * rwarp + lane;
                if (lane < 4) {
                    float p0 = sRaw[0*8+t], p1 = sRaw[1*8+t], p2 = sRaw[2*8+t], p3 = sRaw[3*8+t];
                    float mp = fmaxf(fmaxf(p0, p1), fmaxf(p2, p3));
                    p0 = __expf(p0 - mp); p1 = __expf(p1 - mp);
                    p2 = __expf(p2 - mp); p3 = __expf(p3 - mp);
                    float isp = __fdividef(1.f, p0 + p1 + p2 + p3);
                    p0 *= isp; p1 *= isp; p2 *= isp; p3 *= isp;

                    float q0 = sRaw[4*8+t], q1 = sRaw[5*8+t], q2 = sRaw[6*8+t], q3 = sRaw[7*8+t];
                    float mq = fmaxf(fmaxf(q0, q1), fmaxf(q2, q3));
                    q0 = __expf(q0 - mq); q1 = __expf(q1 - mq);
                    q2 = __expf(q2 - mq); q3 = __expf(q3 - mq);
                    float isq = __fdividef(1.f, q0 + q1 + q2 + q3);
                    q0 *= isq; q1 *= isq; q2 *= isq; q3 *= isq;

                    float av[16];
                    #pragma unroll
                    for (int i = 0; i < 4; i++)
                        #pragma unroll
                        for (int j = 0; j < 4; j++)
                            av[i*4+j] = __expf(sRaw[(8 + i*4 + j)*8 + t] + (i == j ? 2.0f : -2.0f));

                    #pragma unroll
                    for (int itn = 0; itn < 4; itn++) {
                        #pragma unroll
                        for (int i = 0; i < 4; i++) {
                            float rs  = av[i*4] + av[i*4+1] + av[i*4+2] + av[i*4+3];
                            float inv = __fdividef(1.f, fmaxf(rs, EPSV));
                            av[i*4] *= inv; av[i*4+1] *= inv; av[i*4+2] *= inv; av[i*4+3] *= inv;
                        }
                        #pragma unroll
                        for (int j = 0; j < 4; j++) {
                            float cs  = av[j] + av[4+j] + av[8+j] + av[12+j];
                            float inv = __fdividef(1.f, fmaxf(cs, EPSV));
                            av[j] *= inv; av[4+j] *= inv; av[8+j] *= inv; av[12+j] *= inv;
                        }
                    }

                    const float pre[4]  = {p0, p1, p2, p3};
                    const float post[4] = {q0, q1, q2, q3};
                    #pragma unroll
                    for (int i = 0; i < 4; i++)
                        #pragma unroll
                        for (int j = 0; j < 4; j++)
                            sM[t * 16 + i * 4 + j] = av[i*4+j] + post[i] * pre[j];
                }
            }
            BAR_ARRIVE(3 + s);                        // publish sM[s]
        }
    }
}

extern "C" void kernel_launch(void* const* d_in, const int* in_sizes, int n_in,
                              void* d_out, int out_size)
{
    const float* x  = (const float*)d_in[0];
    const float* Wr = (const float*)d_in[1];
    const float* br = (const float*)d_in[2];
    float* out = (float*)d_out;

    int ntok = in_sizes[0] / (WS * DDIM);   // 8192

    cudaFuncSetAttribute(mchc_kernel,
                         cudaFuncAttributeMaxDynamicSharedMemorySize, SMEM_BYTES);

    int sms = 148, dev = 0;
    if (cudaGetDevice(&dev) == cudaSuccess) {
        int v = 0;
        if (cudaDeviceGetAttribute(&v, cudaDevAttrMultiProcessorCount, dev) == cudaSuccess && v > 0)
            sms = v;
    }
    int ngroups = (ntok + G - 1) / G;
    int grid = (ngroups < sms) ? ngroups : sms;

    mchc_kernel<<<grid, THREADS, SMEM_BYTES>>>(x, Wr, br, out, ntok);
}

// round 10
// speedup vs baseline: 1.1466x; 1.1466x over previous
#include <cuda_runtime.h>
#include <cuda_bf16.h>

// ManifoldConstrainedHyperConnection — fused, G=4, R5 dataflow at double
// occupancy: 1024 threads/CTA, each thread owns a 2-float d-slice, 32 warps
// per SM (occ 50%) to hide phase latencies that bounded the 512-thread
// variant. Byte traffic identical to R5; register peak ~56 < 64-reg cap.
//
// Per group: [A: ld.cg x -> stream means] -> [B: 24 Wr rows (LDS.64) x 4
// tokens -> 3x 32-value shuffle butterflies -> sP] -> barA -> [L2 prefetch
// next group] -> [warps 0-2 reduce over 32 warps; warps 0-1 scalar
// softmax+sinkhorn -> M] -> barB -> [F: mix + store, same iteration
// (x re-read = L2 hit)].

#define WRK 24
#define DDIM 2048
#define WS 4
#define THREADS 1024
#define NW 32
#define G 4
#define EPSV 1e-6f

#define SMEM_WR (WRK * DDIM)            // 49152 floats (192 KB)
#define SP_STRIDE 100
#define SMEM_SP (NW * SP_STRIDE)        // 3200 floats
#define SMEM_FLOATS (SMEM_WR + SMEM_SP + 96 + 64)
#define SMEM_BYTES (SMEM_FLOATS * 4)    // ~206 KB

#define FULLM 0xffffffffu

__device__ __forceinline__ float2 ld_cg2(const float* p) {
    return __ldcg(reinterpret_cast<const float2*>(p));
}

// butterfly step: values r[0..n-1] -> r[0..n/2-1]
#define BFLY_STEP(r, n, o)                                              \
    {                                                                   \
        const bool hi_ = (lane & (o)) != 0;                             \
        _Pragma("unroll")                                               \
        for (int v_ = 0; v_ < (n) / 2; v_++) {                          \
            float mine_  = hi_ ? r[v_ + (n) / 2] : r[v_];               \
            float other_ = hi_ ? r[v_] : r[v_ + (n) / 2];               \
            r[v_] = mine_ + __shfl_xor_sync(FULLM, other_, (o));        \
        }                                                               \
    }

__global__ void __launch_bounds__(THREADS, 1)
mchc_kernel(const float* __restrict__ x, const float* __restrict__ Wr,
            const float* __restrict__ br, float* __restrict__ out, int ntok)
{
    extern __shared__ float sm[];
    float* sWr  = sm;
    float* sP   = sm + SMEM_WR;
    float* sRaw = sP + SMEM_SP;      // 96 floats, raw index v = 4k + t
    float* sM   = sRaw + 96;         // 64 floats: sM[t*16 + i*4 + j]

    const int tid  = threadIdx.x;
    const int lane = tid & 31;
    const int warp = tid >> 5;
    const int d0   = tid * 2;        // 2-float d-slice

    // stage W_router into smem once
    for (int i = tid * 4; i < SMEM_WR; i += THREADS * 4)
        *reinterpret_cast<float4*>(sWr + i) = *reinterpret_cast<const float4*>(Wr + i);
    __syncthreads();

    const int ngroups = (ntok + G - 1) / G;

    for (int g = blockIdx.x; g < ngroups; g += gridDim.x) {
        const int n0 = g * G;

        // ---- A: pass-1 read (L2-warm from prefetch) -> stream means ----
        float2 mx[G];
        #pragma unroll
        for (int t = 0; t < G; t++) {
            mx[t] = make_float2(0.f, 0.f);
            if (n0 + t < ntok) {
                const float* p = x + (size_t)(n0 + t) * (WS * DDIM) + d0;
                #pragma unroll
                for (int w = 0; w < WS; w++) {
                    float2 v = ld_cg2(p + w * DDIM);
                    mx[t].x += v.x; mx[t].y += v.y;
                }
                mx[t].x *= 0.25f; mx[t].y *= 0.25f;
            }
        }

        // ---- B: router partials, 3 sets of 32 values (v = 4k + t) ----
        float res0, res1, res2;
        #pragma unroll
        for (int set = 0; set < 3; set++) {
            float a[32];
            #pragma unroll
            for (int kk = 0; kk < 8; kk++) {
                const int k = 8 * set + kk;
                float2 wv = *reinterpret_cast<const float2*>(sWr + k * DDIM + d0);
                #pragma unroll
                for (int t = 0; t < G; t++)
                    a[kk * 4 + t] = wv.x * mx[t].x + wv.y * mx[t].y;
            }
            BFLY_STEP(a, 32, 16)
            BFLY_STEP(a, 16, 8)
            BFLY_STEP(a, 8, 4)
            BFLY_STEP(a, 4, 2)
            BFLY_STEP(a, 2, 1)
            if (set == 0) res0 = a[0];
            else if (set == 1) res1 = a[0];
            else res2 = a[0];
        }
        sP[warp * SP_STRIDE + lane]      = res0;
        sP[warp * SP_STRIDE + 32 + lane] = res1;
        sP[warp * SP_STRIDE + 64 + lane] = res2;
        __syncthreads();                                     // bar A

        // ---- C: warm next group's x into L2 (131072 B = 1024 thr x 128 B) ----
        {
            const int gn = g + gridDim.x;
            if (gn < ngroups) {
                const char* pb = reinterpret_cast<const char*>(
                                     x + (size_t)gn * G * (WS * DDIM)) + tid * 128;
                asm volatile("prefetch.global.L2 [%0];" :: "l"(pb));
            }
        }

        // ---- D: warps 0-2 reduce over 32 warps; warps 0-1 sinkhorn ----
        if (warp < 3) {
            // value v = 32*warp + lane  (= 4k + t, k = 8*warp + lane/4)
            float acc = __ldg(br + 8 * warp + (lane >> 2));
            #pragma unroll
            for (int w = 0; w < NW; w++)
                acc += sP[w * SP_STRIDE + 32 * warp + lane];
            sRaw[32 * warp + lane] = acc;
            asm volatile("bar.sync 1, 96;" ::: "memory");   // warps 0-2 only
        }

        if (warp < 2) {
            const int t = warp * 2 + (lane >> 4);   // token 0..3

            float p0 = sRaw[0*4+t], p1 = sRaw[1*4+t], p2 = sRaw[2*4+t], p3 = sRaw[3*4+t];
            float mp = fmaxf(fmaxf(p0, p1), fmaxf(p2, p3));
            p0 = __expf(p0 - mp); p1 = __expf(p1 - mp);
            p2 = __expf(p2 - mp); p3 = __expf(p3 - mp);
            float isp = __fdividef(1.f, p0 + p1 + p2 + p3);
            p0 *= isp; p1 *= isp; p2 *= isp; p3 *= isp;

            float q0 = sRaw[4*4+t], q1 = sRaw[5*4+t], q2 = sRaw[6*4+t], q3 = sRaw[7*4+t];
            float mq = fmaxf(fmaxf(q0, q1), fmaxf(q2, q3));
            q0 = __expf(q0 - mq); q1 = __expf(q1 - mq);
            q2 = __expf(q2 - mq); q3 = __expf(q3 - mq);
            float isq = __fdividef(1.f, q0 + q1 + q2 + q3);
            q0 *= isq; q1 *= isq; q2 *= isq; q3 *= isq;

            float av[16];
            #pragma unroll
            for (int i = 0; i < 4; i++)
                #pragma unroll
                for (int j = 0; j < 4; j++)
                    av[i*4+j] = __expf(sRaw[(8 + i*4 + j)*4 + t] + (i == j ? 2.0f : -2.0f));

            #pragma unroll
            for (int it = 0; it < 4; it++) {
                #pragma unroll
                for (int i = 0; i < 4; i++) {
                    float rs  = av[i*4] + av[i*4+1] + av[i*4+2] + av[i*4+3];
                    float inv = __fdividef(1.f, fmaxf(rs, EPSV));
                    av[i*4] *= inv; av[i*4+1] *= inv; av[i*4+2] *= inv; av[i*4+3] *= inv;
                }
                #pragma unroll
                for (int j = 0; j < 4; j++) {
                    float cs  = av[j] + av[4+j] + av[8+j] + av[12+j];
                    float inv = __fdividef(1.f, fmaxf(cs, EPSV));
                    av[j] *= inv; av[4+j] *= inv; av[8+j] *= inv; av[12+j] *= inv;
                }
            }

            if ((lane & 15) == 0) {
                const float pre[4]  = {p0, p1, p2, p3};
                const float post[4] = {q0, q1, q2, q3};
                #pragma unroll
                for (int i = 0; i < 4; i++) {
                    float4 mrow;
                    mrow.x = av[i*4+0] + post[i] * pre[0];
                    mrow.y = av[i*4+1] + post[i] * pre[1];
                    mrow.z = av[i*4+2] + post[i] * pre[2];
                    mrow.w = av[i*4+3] + post[i] * pre[3];
                    *reinterpret_cast<float4*>(sM + t * 16 + i * 4) = mrow;
                }
            }
        }
        __syncthreads();                                     // bar B

        // ---- F: mix + store (x re-read is an L2 hit, same iteration) ----
        #pragma unroll
        for (int t = 0; t < G; t++) {
            if (n0 + t < ntok) {
                const float* p = x + (size_t)(n0 + t) * (WS * DDIM) + d0;
                float*       o = out + (size_t)(n0 + t) * (WS * DDIM) + d0;
                float2 x0 = ld_cg2(p);
                float2 x1 = ld_cg2(p + DDIM);
                float2 x2 = ld_cg2(p + 2 * DDIM);
                float2 x3 = ld_cg2(p + 3 * DDIM);
                #pragma unroll
                for (int i = 0; i < WS; i++) {
                    float4 Mi = *reinterpret_cast<const float4*>(sM + t * 16 + i * 4);
                    float2 ov;
                    ov.x = Mi.x*x0.x + Mi.y*x1.x + Mi.z*x2.x + Mi.w*x3.x;
                    ov.y = Mi.x*x0.y + Mi.y*x1.y + Mi.z*x2.y + Mi.w*x3.y;
                    __stcs(reinterpret_cast<float2*>(o + i * DDIM), ov);
                }
            }
        }
        // next iteration's bar A orders sP/sRaw/sM reuse.
    }
}

extern "C" void kernel_launch(void* const* d_in, const int* in_sizes, int n_in,
                              void* d_out, int out_size)
{
    const float* x  = (const float*)d_in[0];
    const float* Wr = (const float*)d_in[1];
    const float* br = (const float*)d_in[2];
    float* out = (float*)d_out;

    int ntok = in_sizes[0] / (WS * DDIM);   // 8192

    cudaFuncSetAttribute(mchc_kernel,
                         cudaFuncAttributeMaxDynamicSharedMemorySize, SMEM_BYTES);

    int sms = 148, dev = 0;
    if (cudaGetDevice(&dev) == cudaSuccess) {
        int v = 0;
        if (cudaDeviceGetAttribute(&v, cudaDevAttrMultiProcessorCount, dev) == cudaSuccess && v > 0)
            sms = v;
    }
    int ngroups = (ntok + G - 1) / G;
    int grid = (ngroups < sms) ? ngroups : sms;

    mchc_kernel<<<grid, THREADS, SMEM_BYTES>>>(x, Wr, br, out, ntok);
}